// round 13
// baseline (speedup 1.0000x reference)
#include <cuda_runtime.h>
#include <cuda_fp16.h>
#include <cstdint>

// out = x @ (w1@w2@w3@w4) per expert, rank-512 factored:
//   P = w2@w3, V^T = w4^T@P^T (prep, 2-term fp16), then
//   h = x@w1 (1-term), out = h@V (1-term).
// R13: 1-term GEMMs get CTA 128x256 / 512 threads (68 flops/byte, was 52);
//      big GEMM moved to launch idx 3 so ncu finally captures it.

#define NE 8
#define NT 4096
#define NH 1024
#define NI 512

// ---------------- scratch ----------------
__device__ __align__(128) __half g_xh[NE*NT*NH];                      // x hi
__device__ __align__(128) __half g_w1th[NE*NI*NH];                    // w1^T hi [E,512,1024]
__device__ __align__(128) __half g_w2h[NE*NI*NH];                     // w2 hi   [E,512,1024]
__device__ __align__(128) __half g_w3th[NE*NI*NH], g_w3tl[NE*NI*NH];  // w3^T hi/lo
__device__ __align__(128) __half g_w4th[NE*NH*NI];                    // w4^T hi [E,1024,512]
__device__ __align__(128) __half g_Ph[NE*NI*NI],   g_Pl[NE*NI*NI];    // P = w2@w3 hi/lo
__device__ __align__(128) __half g_Vth[NE*NH*NI];                     // V^T hi  [E,1024,512]
__device__ __align__(128) __half g_h[NE*NT*NI];                       // h hi    [E,4096,512]

__device__ __forceinline__ void split1(float v, __half& h, __half& l) {
    h = __float2half(v);
    l = __float2half(v - __half2float(h));
}

// ---------------- conversion kernels ----------------
__global__ __launch_bounds__(256)
void half_rm(const float4* __restrict__ in, uint2* __restrict__ hi, int n4) {
    int i = blockIdx.x * 256 + threadIdx.x;
    if (i >= n4) return;
    float4 v = in[i];
    __half h[4] = {__float2half(v.x), __float2half(v.y),
                   __float2half(v.z), __float2half(v.w)};
    hi[i] = *(uint2*)h;
}

// in: [E, R, C] fp32 -> out hi: [E, C, R]
__global__ __launch_bounds__(256)
void half_tr(const float* __restrict__ in, __half* __restrict__ hi, int R, int C) {
    __shared__ float t[32][33];
    const int e = blockIdx.z;
    const float* ine = in + (size_t)e * R * C;
    __half* he = hi + (size_t)e * R * C;
    const int r0 = blockIdx.y * 32, c0 = blockIdx.x * 32;
    const int tx = threadIdx.x & 31, ty = threadIdx.x >> 5;
    #pragma unroll
    for (int i = 0; i < 32; i += 8)
        t[ty + i][tx] = ine[(size_t)(r0 + ty + i) * C + c0 + tx];
    __syncthreads();
    #pragma unroll
    for (int i = 0; i < 32; i += 8)
        he[(size_t)(c0 + ty + i) * R + r0 + tx] = __float2half(t[tx][ty + i]);
}

// in: [E, R, C] fp32 -> out hi/lo: [E, C, R]
__global__ __launch_bounds__(256)
void split_tr(const float* __restrict__ in, __half* __restrict__ hi,
              __half* __restrict__ lo, int R, int C) {
    __shared__ float t[32][33];
    const int e = blockIdx.z;
    const float* ine = in + (size_t)e * R * C;
    __half* he = hi + (size_t)e * R * C;
    __half* le = lo + (size_t)e * R * C;
    const int r0 = blockIdx.y * 32, c0 = blockIdx.x * 32;
    const int tx = threadIdx.x & 31, ty = threadIdx.x >> 5;
    #pragma unroll
    for (int i = 0; i < 32; i += 8)
        t[ty + i][tx] = ine[(size_t)(r0 + ty + i) * C + c0 + tx];
    __syncthreads();
    #pragma unroll
    for (int i = 0; i < 32; i += 8) {
        __half h, l;
        split1(t[tx][ty + i], h, l);
        he[(size_t)(c0 + ty + i) * R + r0 + tx] = h;
        le[(size_t)(c0 + ty + i) * R + r0 + tx] = l;
    }
}

// ---------------- common HMMA pieces ----------------
#define BKC 32
#define ROWB 80u
#define TILEB (128u * ROWB)       // 10240 B per 128x32 tile

__device__ __forceinline__ void cp16(uint32_t s, const void* g) {
    asm volatile("cp.async.cg.shared.global [%0], [%1], 16;" :: "r"(s), "l"(g));
}
__device__ __forceinline__ void ldm4(uint32_t* r, uint32_t addr) {
    asm volatile("ldmatrix.sync.aligned.m8n8.x4.shared.b16 {%0,%1,%2,%3}, [%4];"
                 : "=r"(r[0]), "=r"(r[1]), "=r"(r[2]), "=r"(r[3]) : "r"(addr));
}
__device__ __forceinline__ void mma16816(float* c, const uint32_t* a, uint32_t b0, uint32_t b1) {
    asm volatile("mma.sync.aligned.m16n8k16.row.col.f32.f16.f16.f32 "
                 "{%0,%1,%2,%3}, {%4,%5,%6,%7}, {%8,%9}, {%0,%1,%2,%3};"
                 : "+f"(c[0]), "+f"(c[1]), "+f"(c[2]), "+f"(c[3])
                 : "r"(a[0]), "r"(a[1]), "r"(a[2]), "r"(a[3]), "r"(b0), "r"(b1));
}

// ---------------- 2-term GEMM (prep): CTA 128x128, 256 thr ----------------
#define BM 128
#define BN 128
#define SMEM_2T (3u * 3u * TILEB)   // 92160

template<int OUTMODE>   // 1 = split hi/lo, 2 = hi only
__global__ __launch_bounds__(256, 2)
void gemm_2t(const __half* __restrict__ Ah,
             const __half* __restrict__ Bh, const __half* __restrict__ Bl,
             __half* __restrict__ Ch, __half* __restrict__ Cl,
             int M, int N, int K)
{
    constexpr uint32_t BUFB = 3u * TILEB;
    constexpr int NST = 3;

    extern __shared__ __align__(128) char smem[];
    const uint32_t sb = (uint32_t)__cvta_generic_to_shared(smem);

    const int tid = threadIdx.x;
    const int lane = tid & 31;
    const int wid = tid >> 5;
    const int wm = (wid >> 2) * 64;
    const int wn = (wid & 3) * 32;
    const int g = lane >> 3, r8 = lane & 7;

    const int e = blockIdx.z;
    const size_t MK = (size_t)M * K, NK = (size_t)N * K, MN = (size_t)M * N;
    const __half *Ahe = Ah + e * MK;
    const __half *Bhe = Bh + e * NK, *Ble = Bl + e * NK;
    const int bm = blockIdx.y * BM, bn = blockIdx.x * BN;

    float acc[4][4][4];
    #pragma unroll
    for (int i = 0; i < 4; i++)
        #pragma unroll
        for (int j = 0; j < 4; j++)
            #pragma unroll
            for (int q = 0; q < 4; q++) acc[i][j][q] = 0.0f;

    const int NC = K / BKC;
    const int cr0 = tid >> 2,          cc0 = tid & 3;
    const int cr1 = (tid + 256) >> 2,  cc1 = (tid + 256) & 3;

    auto load_chunk = [&](int c, int buf) {
        const int k0 = c * BKC;
        const uint32_t b = sb + (uint32_t)buf * BUFB;
        cp16(b + cr0 * ROWB + cc0 * 16, Ahe + (size_t)(bm + cr0) * K + k0 + cc0 * 8);
        cp16(b + cr1 * ROWB + cc1 * 16, Ahe + (size_t)(bm + cr1) * K + k0 + cc1 * 8);
        cp16(b + TILEB + cr0 * ROWB + cc0 * 16, Bhe + (size_t)(bn + cr0) * K + k0 + cc0 * 8);
        cp16(b + TILEB + cr1 * ROWB + cc1 * 16, Bhe + (size_t)(bn + cr1) * K + k0 + cc1 * 8);
        cp16(b + 2 * TILEB + cr0 * ROWB + cc0 * 16, Ble + (size_t)(bn + cr0) * K + k0 + cc0 * 8);
        cp16(b + 2 * TILEB + cr1 * ROWB + cc1 * 16, Ble + (size_t)(bn + cr1) * K + k0 + cc1 * 8);
        asm volatile("cp.async.commit_group;" ::: "memory");
    };

    load_chunk(0, 0);
    load_chunk(1, 1);

    for (int c = 0; c < NC; c++) {
        asm volatile("cp.async.wait_group 1;" ::: "memory");
        __syncthreads();
        if (c + 2 < NC) load_chunk(c + 2, (c + 2) % NST);
        else asm volatile("cp.async.commit_group;" ::: "memory");

        const uint32_t As = sb + (uint32_t)(c % NST) * BUFB;
        const uint32_t Bs  = As + TILEB;
        const uint32_t Bls = As + 2 * TILEB;

        #pragma unroll
        for (int ks = 0; ks < 2; ks++) {
            uint32_t ah[4][4], bbh[2][4], bbl[2][4];
            #pragma unroll
            for (int ti = 0; ti < 4; ti++) {
                uint32_t off = (uint32_t)(wm + ti * 16 + (g & 1) * 8 + r8) * ROWB
                             + ks * 32 + (g >> 1) * 16;
                ldm4(ah[ti], As + off);
            }
            #pragma unroll
            for (int p = 0; p < 2; p++) {
                uint32_t off = (uint32_t)(wn + p * 16 + (g >> 1) * 8 + r8) * ROWB
                             + ks * 32 + (g & 1) * 16;
                ldm4(bbh[p], Bs + off);
                ldm4(bbl[p], Bls + off);
            }
            #pragma unroll
            for (int ti = 0; ti < 4; ti++)
                #pragma unroll
                for (int tj = 0; tj < 4; tj++) {
                    mma16816(acc[ti][tj], ah[ti],
                             bbh[tj >> 1][(tj & 1) * 2], bbh[tj >> 1][(tj & 1) * 2 + 1]);
                    mma16816(acc[ti][tj], ah[ti],
                             bbl[tj >> 1][(tj & 1) * 2], bbl[tj >> 1][(tj & 1) * 2 + 1]);
                }
        }
    }

    #pragma unroll
    for (int ti = 0; ti < 4; ti++)
        #pragma unroll
        for (int tj = 0; tj < 4; tj++) {
            const int row = bm + wm + ti * 16 + (lane >> 2);
            const int col = bn + wn + tj * 8 + (lane & 3) * 2;
            if (OUTMODE == 1) {
                __half h0, l0, h1, l1;
                split1(acc[ti][tj][0], h0, l0); split1(acc[ti][tj][1], h1, l1);
                __half hp[2] = {h0, h1}, lp[2] = {l0, l1};
                *(uint32_t*)(Ch + e * MN + (size_t)row * N + col) = *(uint32_t*)hp;
                *(uint32_t*)(Cl + e * MN + (size_t)row * N + col) = *(uint32_t*)lp;
                split1(acc[ti][tj][2], h0, l0); split1(acc[ti][tj][3], h1, l1);
                __half hq[2] = {h0, h1}, lq[2] = {l0, l1};
                *(uint32_t*)(Ch + e * MN + (size_t)(row + 8) * N + col) = *(uint32_t*)hq;
                *(uint32_t*)(Cl + e * MN + (size_t)(row + 8) * N + col) = *(uint32_t*)lq;
            } else {
                __half hp[2] = {__float2half(acc[ti][tj][0]), __float2half(acc[ti][tj][1])};
                __half hq[2] = {__float2half(acc[ti][tj][2]), __float2half(acc[ti][tj][3])};
                *(uint32_t*)(Ch + e * MN + (size_t)row * N + col) = *(uint32_t*)hp;
                *(uint32_t*)(Ch + e * MN + (size_t)(row + 8) * N + col) = *(uint32_t*)hq;
            }
        }
}

// ---------------- 1-term wide GEMM: CTA 128x256, 512 thr ----------------
// 16 warps: 2(M) x 8(N); warp tile 64x32. Stage = A(10240) + B(20480) = 30720.
#define BM2 128
#define BN2 256
#define ATILE 10240u
#define BUF1 30720u
#define SMEM_1T (3u * BUF1)      // 92160

template<int OUTMODE>   // 0 = fp32, 2 = hi only
__global__ __launch_bounds__(512, 1)
void gemm_1t_wide(const __half* __restrict__ Ah, const __half* __restrict__ Bh,
                  float* __restrict__ Cf, __half* __restrict__ Ch,
                  int M, int N, int K)
{
    constexpr int NST = 3;

    extern __shared__ __align__(128) char smem[];
    const uint32_t sb = (uint32_t)__cvta_generic_to_shared(smem);

    const int tid = threadIdx.x;
    const int lane = tid & 31;
    const int wid = tid >> 5;
    const int wm = (wid >> 3) * 64;   // 2 M groups
    const int wn = (wid & 7) * 32;    // 8 N groups
    const int g = lane >> 3, r8 = lane & 7;

    const int e = blockIdx.z;
    const size_t MK = (size_t)M * K, NK = (size_t)N * K, MN = (size_t)M * N;
    const __half *Ahe = Ah + e * MK;
    const __half *Bhe = Bh + e * NK;
    const int bm = blockIdx.y * BM2, bn = blockIdx.x * BN2;

    float acc[4][4][4];
    #pragma unroll
    for (int i = 0; i < 4; i++)
        #pragma unroll
        for (int j = 0; j < 4; j++)
            #pragma unroll
            for (int q = 0; q < 4; q++) acc[i][j][q] = 0.0f;

    const int NC = K / BKC;
    const int rr = tid >> 2, rc = tid & 3;   // 128 rows x 4 chunks (A); B rows rr, rr+128

    auto load_chunk = [&](int c, int buf) {
        const int k0 = c * BKC;
        const uint32_t b = sb + (uint32_t)buf * BUF1;
        cp16(b + rr * ROWB + rc * 16, Ahe + (size_t)(bm + rr) * K + k0 + rc * 8);
        cp16(b + ATILE + rr * ROWB + rc * 16, Bhe + (size_t)(bn + rr) * K + k0 + rc * 8);
        cp16(b + ATILE + (rr + 128) * ROWB + rc * 16,
             Bhe + (size_t)(bn + rr + 128) * K + k0 + rc * 8);
        asm volatile("cp.async.commit_group;" ::: "memory");
    };

    load_chunk(0, 0);
    load_chunk(1, 1);

    for (int c = 0; c < NC; c++) {
        asm volatile("cp.async.wait_group 1;" ::: "memory");
        __syncthreads();
        if (c + 2 < NC) load_chunk(c + 2, (c + 2) % NST);
        else asm volatile("cp.async.commit_group;" ::: "memory");

        const uint32_t As = sb + (uint32_t)(c % NST) * BUF1;
        const uint32_t Bs = As + ATILE;

        #pragma unroll
        for (int ks = 0; ks < 2; ks++) {
            uint32_t ah[4][4], bbh[2][4];
            #pragma unroll
            for (int ti = 0; ti < 4; ti++) {
                uint32_t off = (uint32_t)(wm + ti * 16 + (g & 1) * 8 + r8) * ROWB
                             + ks * 32 + (g >> 1) * 16;
                ldm4(ah[ti], As + off);
            }
            #pragma unroll
            for (int p = 0; p < 2; p++) {
                uint32_t off = (uint32_t)(wn + p * 16 + (g >> 1) * 8 + r8) * ROWB
                             + ks * 32 + (g & 1) * 16;
                ldm4(bbh[p], Bs + off);
            }
            #pragma unroll
            for (int ti = 0; ti < 4; ti++)
                #pragma unroll
                for (int tj = 0; tj < 4; tj++)
                    mma16816(acc[ti][tj], ah[ti],
                             bbh[tj >> 1][(tj & 1) * 2], bbh[tj >> 1][(tj & 1) * 2 + 1]);
        }
    }

    #pragma unroll
    for (int ti = 0; ti < 4; ti++)
        #pragma unroll
        for (int tj = 0; tj < 4; tj++) {
            const int row = bm + wm + ti * 16 + (lane >> 2);
            const int col = bn + wn + tj * 8 + (lane & 3) * 2;
            if (OUTMODE == 2) {
                __half hp[2] = {__float2half(acc[ti][tj][0]), __float2half(acc[ti][tj][1])};
                __half hq[2] = {__float2half(acc[ti][tj][2]), __float2half(acc[ti][tj][3])};
                *(uint32_t*)(Ch + e * MN + (size_t)row * N + col) = *(uint32_t*)hp;
                *(uint32_t*)(Ch + e * MN + (size_t)(row + 8) * N + col) = *(uint32_t*)hq;
            } else {
                float* cp0 = Cf + e * MN + (size_t)row * N + col;
                float* cp1 = Cf + e * MN + (size_t)(row + 8) * N + col;
                *(float2*)cp0 = make_float2(acc[ti][tj][0], acc[ti][tj][1]);
                *(float2*)cp1 = make_float2(acc[ti][tj][2], acc[ti][tj][3]);
            }
        }
}

// ---------------- launcher ----------------
extern "C" void kernel_launch(void* const* d_in, const int* in_sizes, int n_in,
                              void* d_out, int out_size)
{
    (void)in_sizes; (void)n_in; (void)out_size;
    const float* x  = (const float*)d_in[0];
    const float* w1 = (const float*)d_in[1];
    const float* w2 = (const float*)d_in[2];
    const float* w3 = (const float*)d_in[3];
    const float* w4 = (const float*)d_in[4];
    float* out = (float*)d_out;

    __half *xh,*w1th,*w2h,*w3th,*w3tl,*w4th,*Ph,*Pl,*Vth,*hbuf;
    cudaGetSymbolAddress((void**)&xh,   g_xh);
    cudaGetSymbolAddress((void**)&w1th, g_w1th);
    cudaGetSymbolAddress((void**)&w2h,  g_w2h);
    cudaGetSymbolAddress((void**)&w3th, g_w3th); cudaGetSymbolAddress((void**)&w3tl, g_w3tl);
    cudaGetSymbolAddress((void**)&w4th, g_w4th);
    cudaGetSymbolAddress((void**)&Ph,   g_Ph);   cudaGetSymbolAddress((void**)&Pl,   g_Pl);
    cudaGetSymbolAddress((void**)&Vth,  g_Vth);
    cudaGetSymbolAddress((void**)&hbuf, g_h);

    cudaFuncSetAttribute(gemm_2t<1>, cudaFuncAttributeMaxDynamicSharedMemorySize, SMEM_2T);
    cudaFuncSetAttribute(gemm_2t<2>, cudaFuncAttributeMaxDynamicSharedMemorySize, SMEM_2T);
    cudaFuncSetAttribute(gemm_1t_wide<0>, cudaFuncAttributeMaxDynamicSharedMemorySize, SMEM_1T);
    cudaFuncSetAttribute(gemm_1t_wide<2>, cudaFuncAttributeMaxDynamicSharedMemorySize, SMEM_1T);

    // idx 0: w1 -> w1^T hi
    half_tr<<<dim3(NI / 32, NH / 32, NE), 256>>>(w1, w1th, NH, NI);
    // idx 1: x hi
    {
        int n4 = NE * NT * NH / 4;
        half_rm<<<n4 / 256, 256>>>((const float4*)x, (uint2*)xh, n4);
    }
    // idx 2: w3 -> w3^T hi/lo
    split_tr<<<dim3(NI / 32, NH / 32, NE), 256>>>(w3, w3th, w3tl, NH, NI);
    // idx 3 (ncu capture): h = x @ w1 (1-term wide)  M=4096, N=512, K=1024
    gemm_1t_wide<2><<<dim3(NI / BN2, NT / BM2, NE), 512, SMEM_1T>>>(
        xh, w1th, nullptr, hbuf, NT, NI, NH);
    // idx 4: w2 hi
    {
        int n4 = NE * NI * NH / 4;
        half_rm<<<n4 / 256, 256>>>((const float4*)w2, (uint2*)w2h, n4);
    }
    // idx 5: P = w2 @ w3 (2-term, split out)  M=N=512, K=1024
    gemm_2t<1><<<dim3(NI / BN, NI / BM, NE), 256, SMEM_2T>>>(
        w2h, w3th, w3tl, Ph, Pl, NI, NI, NH);
    // idx 6: w4 -> w4^T hi
    half_tr<<<dim3(NH / 32, NI / 32, NE), 256>>>(w4, w4th, NI, NH);
    // idx 7: V^T = w4^T @ P^T (2-term, hi out)  M=1024, N=512, K=512
    gemm_2t<2><<<dim3(NI / BN, NH / BM, NE), 256, SMEM_2T>>>(
        w4th, Ph, Pl, Vth, nullptr, NH, NI, NI);
    // idx 8: out = h @ V (1-term wide, fp32 out)  M=4096, N=1024, K=512
    gemm_1t_wide<0><<<dim3(NH / BN2, NT / BM2, NE), 512, SMEM_1T>>>(
        hbuf, Vth, out, nullptr, NT, NH, NI);
}

// round 14
// speedup vs baseline: 1.6623x; 1.6623x over previous
#include <cuda_runtime.h>
#include <cuda_fp16.h>
#include <cstdint>

// out = x @ (w1@w2@w3@w4) per expert, rank-512 factored:
//   P = w2@w3, V^T = w4^T@P^T (prep, 2-term fp16), then
//   h = x@w1 (1-term), out = h@V (1-term).
// R14: 1-term GEMMs back to 128x128/256thr/2CTA-per-SM but with a 5-stage
// cp.async ring + wait_group 3 (3 fetches in flight) — attack the fetch-latency
// floor diagnosed in R13 (tensor=40%, issue=15.6%, no memory unit saturated).

#define NE 8
#define NT 4096
#define NH 1024
#define NI 512

// ---------------- scratch ----------------
__device__ __align__(128) __half g_xh[NE*NT*NH];                      // x hi
__device__ __align__(128) __half g_w1th[NE*NI*NH];                    // w1^T hi [E,512,1024]
__device__ __align__(128) __half g_w2h[NE*NI*NH];                     // w2 hi   [E,512,1024]
__device__ __align__(128) __half g_w3th[NE*NI*NH], g_w3tl[NE*NI*NH];  // w3^T hi/lo
__device__ __align__(128) __half g_w4th[NE*NH*NI];                    // w4^T hi [E,1024,512]
__device__ __align__(128) __half g_Ph[NE*NI*NI],   g_Pl[NE*NI*NI];    // P = w2@w3 hi/lo
__device__ __align__(128) __half g_Vth[NE*NH*NI];                     // V^T hi  [E,1024,512]
__device__ __align__(128) __half g_h[NE*NT*NI];                       // h hi    [E,4096,512]

__device__ __forceinline__ void split1(float v, __half& h, __half& l) {
    h = __float2half(v);
    l = __float2half(v - __half2float(h));
}

// ---------------- conversion kernels ----------------
__global__ __launch_bounds__(256)
void half_rm(const float4* __restrict__ in, uint2* __restrict__ hi, int n4) {
    int i = blockIdx.x * 256 + threadIdx.x;
    if (i >= n4) return;
    float4 v = in[i];
    __half h[4] = {__float2half(v.x), __float2half(v.y),
                   __float2half(v.z), __float2half(v.w)};
    hi[i] = *(uint2*)h;
}

// in: [E, R, C] fp32 -> out hi: [E, C, R]
__global__ __launch_bounds__(256)
void half_tr(const float* __restrict__ in, __half* __restrict__ hi, int R, int C) {
    __shared__ float t[32][33];
    const int e = blockIdx.z;
    const float* ine = in + (size_t)e * R * C;
    __half* he = hi + (size_t)e * R * C;
    const int r0 = blockIdx.y * 32, c0 = blockIdx.x * 32;
    const int tx = threadIdx.x & 31, ty = threadIdx.x >> 5;
    #pragma unroll
    for (int i = 0; i < 32; i += 8)
        t[ty + i][tx] = ine[(size_t)(r0 + ty + i) * C + c0 + tx];
    __syncthreads();
    #pragma unroll
    for (int i = 0; i < 32; i += 8)
        he[(size_t)(c0 + ty + i) * R + r0 + tx] = __float2half(t[tx][ty + i]);
}

// in: [E, R, C] fp32 -> out hi/lo: [E, C, R]
__global__ __launch_bounds__(256)
void split_tr(const float* __restrict__ in, __half* __restrict__ hi,
              __half* __restrict__ lo, int R, int C) {
    __shared__ float t[32][33];
    const int e = blockIdx.z;
    const float* ine = in + (size_t)e * R * C;
    __half* he = hi + (size_t)e * R * C;
    __half* le = lo + (size_t)e * R * C;
    const int r0 = blockIdx.y * 32, c0 = blockIdx.x * 32;
    const int tx = threadIdx.x & 31, ty = threadIdx.x >> 5;
    #pragma unroll
    for (int i = 0; i < 32; i += 8)
        t[ty + i][tx] = ine[(size_t)(r0 + ty + i) * C + c0 + tx];
    __syncthreads();
    #pragma unroll
    for (int i = 0; i < 32; i += 8) {
        __half h, l;
        split1(t[tx][ty + i], h, l);
        he[(size_t)(c0 + ty + i) * R + r0 + tx] = h;
        le[(size_t)(c0 + ty + i) * R + r0 + tx] = l;
    }
}

// ---------------- common HMMA pieces ----------------
#define BM 128
#define BN 128
#define BKC 32
#define ROWB 80u
#define TILEB (128u * ROWB)       // 10240 B per 128x32 tile

__device__ __forceinline__ void cp16(uint32_t s, const void* g) {
    asm volatile("cp.async.cg.shared.global [%0], [%1], 16;" :: "r"(s), "l"(g));
}
__device__ __forceinline__ void ldm4(uint32_t* r, uint32_t addr) {
    asm volatile("ldmatrix.sync.aligned.m8n8.x4.shared.b16 {%0,%1,%2,%3}, [%4];"
                 : "=r"(r[0]), "=r"(r[1]), "=r"(r[2]), "=r"(r[3]) : "r"(addr));
}
__device__ __forceinline__ void mma16816(float* c, const uint32_t* a, uint32_t b0, uint32_t b1) {
    asm volatile("mma.sync.aligned.m16n8k16.row.col.f32.f16.f16.f32 "
                 "{%0,%1,%2,%3}, {%4,%5,%6,%7}, {%8,%9}, {%0,%1,%2,%3};"
                 : "+f"(c[0]), "+f"(c[1]), "+f"(c[2]), "+f"(c[3])
                 : "r"(a[0]), "r"(a[1]), "r"(a[2]), "r"(a[3]), "r"(b0), "r"(b1));
}

// OUTMODE: 0 = fp32, 1 = split hi/lo, 2 = hi only.  NBT: B terms (1 or 2).
// NBT==2: 3-stage ring, wait_group 1 (compute-rich, proven at ~360 TF/s).
// NBT==1: 5-stage ring, wait_group 3 (cover the fetch-latency floor).
template<int OUTMODE, int NBT>
__global__ __launch_bounds__(256, 2)
void gemm_hmma(const __half* __restrict__ Ah,
               const __half* __restrict__ Bh, const __half* __restrict__ Bl,
               float* __restrict__ Cf,
               __half* __restrict__ Ch, __half* __restrict__ Cl,
               int M, int N, int K)
{
    constexpr uint32_t NTILE = 1 + NBT;          // Ah | Bh [| Bl]
    constexpr uint32_t BUFB  = NTILE * TILEB;
    constexpr int      NST   = (NBT == 2) ? 3 : 5;

    extern __shared__ __align__(128) char smem[];
    const uint32_t sb = (uint32_t)__cvta_generic_to_shared(smem);

    const int tid = threadIdx.x;
    const int lane = tid & 31;
    const int wid = tid >> 5;
    const int wm = (wid >> 2) * 64;
    const int wn = (wid & 3) * 32;
    const int g = lane >> 3, r8 = lane & 7;

    const int e = blockIdx.z;
    const size_t MK = (size_t)M * K, NK = (size_t)N * K, MN = (size_t)M * N;
    const __half *Ahe = Ah + e * MK;
    const __half *Bhe = Bh + e * NK, *Ble = (NBT == 2) ? Bl + e * NK : nullptr;
    const int bm = blockIdx.y * BM, bn = blockIdx.x * BN;

    float acc[4][4][4];
    #pragma unroll
    for (int i = 0; i < 4; i++)
        #pragma unroll
        for (int j = 0; j < 4; j++)
            #pragma unroll
            for (int q = 0; q < 4; q++) acc[i][j][q] = 0.0f;

    const int NC = K / BKC;

    const int cr0 = tid >> 2,          cc0 = tid & 3;
    const int cr1 = (tid + 256) >> 2,  cc1 = (tid + 256) & 3;

    auto load_chunk = [&](int c, int buf) {
        const int k0 = c * BKC;
        const uint32_t b = sb + (uint32_t)buf * BUFB;
        cp16(b + cr0 * ROWB + cc0 * 16, Ahe + (size_t)(bm + cr0) * K + k0 + cc0 * 8);
        cp16(b + cr1 * ROWB + cc1 * 16, Ahe + (size_t)(bm + cr1) * K + k0 + cc1 * 8);
        cp16(b + TILEB + cr0 * ROWB + cc0 * 16, Bhe + (size_t)(bn + cr0) * K + k0 + cc0 * 8);
        cp16(b + TILEB + cr1 * ROWB + cc1 * 16, Bhe + (size_t)(bn + cr1) * K + k0 + cc1 * 8);
        if (NBT == 2) {
            cp16(b + 2 * TILEB + cr0 * ROWB + cc0 * 16, Ble + (size_t)(bn + cr0) * K + k0 + cc0 * 8);
            cp16(b + 2 * TILEB + cr1 * ROWB + cc1 * 16, Ble + (size_t)(bn + cr1) * K + k0 + cc1 * 8);
        }
        asm volatile("cp.async.commit_group;" ::: "memory");
    };

    #pragma unroll
    for (int s = 0; s < NST - 1; s++) load_chunk(s, s);

    for (int c = 0; c < NC; c++) {
        asm volatile("cp.async.wait_group %0;" :: "n"(NST - 2) : "memory");
        __syncthreads();
        if (c + NST - 1 < NC) load_chunk(c + NST - 1, (c + NST - 1) % NST);
        else asm volatile("cp.async.commit_group;" ::: "memory");

        const uint32_t As = sb + (uint32_t)(c % NST) * BUFB;
        const uint32_t Bs  = As + TILEB;
        const uint32_t Bls = As + 2 * TILEB;

        #pragma unroll
        for (int ks = 0; ks < 2; ks++) {
            uint32_t ah[4][4], bbh[2][4], bbl[2][4];
            #pragma unroll
            for (int ti = 0; ti < 4; ti++) {
                uint32_t off = (uint32_t)(wm + ti * 16 + (g & 1) * 8 + r8) * ROWB
                             + ks * 32 + (g >> 1) * 16;
                ldm4(ah[ti], As + off);
            }
            #pragma unroll
            for (int p = 0; p < 2; p++) {
                uint32_t off = (uint32_t)(wn + p * 16 + (g >> 1) * 8 + r8) * ROWB
                             + ks * 32 + (g & 1) * 16;
                ldm4(bbh[p], Bs + off);
                if (NBT == 2) ldm4(bbl[p], Bls + off);
            }
            #pragma unroll
            for (int ti = 0; ti < 4; ti++)
                #pragma unroll
                for (int tj = 0; tj < 4; tj++) {
                    mma16816(acc[ti][tj], ah[ti],
                             bbh[tj >> 1][(tj & 1) * 2], bbh[tj >> 1][(tj & 1) * 2 + 1]);
                    if (NBT == 2)
                        mma16816(acc[ti][tj], ah[ti],
                                 bbl[tj >> 1][(tj & 1) * 2], bbl[tj >> 1][(tj & 1) * 2 + 1]);
                }
        }
    }

    // epilogue
    #pragma unroll
    for (int ti = 0; ti < 4; ti++)
        #pragma unroll
        for (int tj = 0; tj < 4; tj++) {
            const int row = bm + wm + ti * 16 + (lane >> 2);
            const int col = bn + wn + tj * 8 + (lane & 3) * 2;
            if (OUTMODE == 1) {
                __half h0, l0, h1, l1;
                split1(acc[ti][tj][0], h0, l0); split1(acc[ti][tj][1], h1, l1);
                __half hp[2] = {h0, h1}, lp[2] = {l0, l1};
                *(uint32_t*)(Ch + e * MN + (size_t)row * N + col) = *(uint32_t*)hp;
                *(uint32_t*)(Cl + e * MN + (size_t)row * N + col) = *(uint32_t*)lp;
                split1(acc[ti][tj][2], h0, l0); split1(acc[ti][tj][3], h1, l1);
                __half hq[2] = {h0, h1}, lq[2] = {l0, l1};
                *(uint32_t*)(Ch + e * MN + (size_t)(row + 8) * N + col) = *(uint32_t*)hq;
                *(uint32_t*)(Cl + e * MN + (size_t)(row + 8) * N + col) = *(uint32_t*)lq;
            } else if (OUTMODE == 2) {
                __half hp[2] = {__float2half(acc[ti][tj][0]), __float2half(acc[ti][tj][1])};
                __half hq[2] = {__float2half(acc[ti][tj][2]), __float2half(acc[ti][tj][3])};
                *(uint32_t*)(Ch + e * MN + (size_t)row * N + col) = *(uint32_t*)hp;
                *(uint32_t*)(Ch + e * MN + (size_t)(row + 8) * N + col) = *(uint32_t*)hq;
            } else {
                float* cp0 = Cf + e * MN + (size_t)row * N + col;
                float* cp1 = Cf + e * MN + (size_t)(row + 8) * N + col;
                *(float2*)cp0 = make_float2(acc[ti][tj][0], acc[ti][tj][1]);
                *(float2*)cp1 = make_float2(acc[ti][tj][2], acc[ti][tj][3]);
            }
        }
}

#define SMEM_2T (3u * 3u * TILEB)   // 92160
#define SMEM_1T (5u * 2u * TILEB)   // 102400 (x2 CTAs = 200KB/SM, fits 228KB)

// ---------------- launcher ----------------
extern "C" void kernel_launch(void* const* d_in, const int* in_sizes, int n_in,
                              void* d_out, int out_size)
{
    (void)in_sizes; (void)n_in; (void)out_size;
    const float* x  = (const float*)d_in[0];
    const float* w1 = (const float*)d_in[1];
    const float* w2 = (const float*)d_in[2];
    const float* w3 = (const float*)d_in[3];
    const float* w4 = (const float*)d_in[4];
    float* out = (float*)d_out;

    __half *xh,*w1th,*w2h,*w3th,*w3tl,*w4th,*Ph,*Pl,*Vth,*hbuf;
    cudaGetSymbolAddress((void**)&xh,   g_xh);
    cudaGetSymbolAddress((void**)&w1th, g_w1th);
    cudaGetSymbolAddress((void**)&w2h,  g_w2h);
    cudaGetSymbolAddress((void**)&w3th, g_w3th); cudaGetSymbolAddress((void**)&w3tl, g_w3tl);
    cudaGetSymbolAddress((void**)&w4th, g_w4th);
    cudaGetSymbolAddress((void**)&Ph,   g_Ph);   cudaGetSymbolAddress((void**)&Pl,   g_Pl);
    cudaGetSymbolAddress((void**)&Vth,  g_Vth);
    cudaGetSymbolAddress((void**)&hbuf, g_h);

    cudaFuncSetAttribute(gemm_hmma<1,2>, cudaFuncAttributeMaxDynamicSharedMemorySize, SMEM_2T);
    cudaFuncSetAttribute(gemm_hmma<2,2>, cudaFuncAttributeMaxDynamicSharedMemorySize, SMEM_2T);
    cudaFuncSetAttribute(gemm_hmma<2,1>, cudaFuncAttributeMaxDynamicSharedMemorySize, SMEM_1T);
    cudaFuncSetAttribute(gemm_hmma<0,1>, cudaFuncAttributeMaxDynamicSharedMemorySize, SMEM_1T);

    // idx 0: w1 -> w1^T hi
    half_tr<<<dim3(NI / 32, NH / 32, NE), 256>>>(w1, w1th, NH, NI);
    // idx 1: x hi
    {
        int n4 = NE * NT * NH / 4;
        half_rm<<<n4 / 256, 256>>>((const float4*)x, (uint2*)xh, n4);
    }
    // idx 2: w3 -> w3^T hi/lo
    split_tr<<<dim3(NI / 32, NH / 32, NE), 256>>>(w3, w3th, w3tl, NH, NI);
    // idx 3 (ncu capture): h = x @ w1 (1-term, 5-stage)  M=4096, N=512, K=1024
    gemm_hmma<2,1><<<dim3(NI / BN, NT / BM, NE), 256, SMEM_1T>>>(
        xh, w1th, nullptr, nullptr, hbuf, nullptr, NT, NI, NH);
    // idx 4: w2 hi
    {
        int n4 = NE * NI * NH / 4;
        half_rm<<<n4 / 256, 256>>>((const float4*)w2, (uint2*)w2h, n4);
    }
    // idx 5: P = w2 @ w3 (2-term, split out)  M=N=512, K=1024
    gemm_hmma<1,2><<<dim3(NI / BN, NI / BM, NE), 256, SMEM_2T>>>(
        w2h, w3th, w3tl, nullptr, Ph, Pl, NI, NI, NH);
    // idx 6: w4 -> w4^T hi
    half_tr<<<dim3(NH / 32, NI / 32, NE), 256>>>(w4, w4th, NI, NH);
    // idx 7: V^T = w4^T @ P^T (2-term, hi out)  M=1024, N=512, K=512
    gemm_hmma<2,2><<<dim3(NI / BN, NH / BM, NE), 256, SMEM_2T>>>(
        w4th, Ph, Pl, nullptr, Vth, nullptr, NH, NI, NI);
    // idx 8: out = h @ V (1-term, 5-stage, fp32 out)  M=4096, N=1024, K=512
    gemm_hmma<0,1><<<dim3(NH / BN, NT / BM, NE), 256, SMEM_1T>>>(
        hbuf, Vth, nullptr, out, nullptr, nullptr, NT, NH, NI);
}

// round 15
// speedup vs baseline: 1.7921x; 1.0781x over previous
#include <cuda_runtime.h>
#include <cuda_fp16.h>
#include <cstdint>

// out = x @ (w1@w2@w3@w4) per expert, rank-512 factored:
//   P = w2@w3, V^T = w4^T@P^T (prep, 2-term fp16), then
//   h = x@w1 (1-term), out = h@V (1-term).
// R15: 1-term GEMMs use BK=64 stages (rows of 144B, 18KB/tile, 36KB/stage,
// 3-stage ring = 110.6KB/CTA, 2 CTAs/SM): 64 MMAs/warp per barrier (2x),
// half the barriers, same prefetch depth. Prep GEMMs unchanged (BKC=32, 2-term).

#define NE 8
#define NT 4096
#define NH 1024
#define NI 512

// ---------------- scratch ----------------
__device__ __align__(128) __half g_xh[NE*NT*NH];                      // x hi
__device__ __align__(128) __half g_w1th[NE*NI*NH];                    // w1^T hi [E,512,1024]
__device__ __align__(128) __half g_w2h[NE*NI*NH];                     // w2 hi   [E,512,1024]
__device__ __align__(128) __half g_w3th[NE*NI*NH], g_w3tl[NE*NI*NH];  // w3^T hi/lo
__device__ __align__(128) __half g_w4th[NE*NH*NI];                    // w4^T hi [E,1024,512]
__device__ __align__(128) __half g_Ph[NE*NI*NI],   g_Pl[NE*NI*NI];    // P = w2@w3 hi/lo
__device__ __align__(128) __half g_Vth[NE*NH*NI];                     // V^T hi  [E,1024,512]
__device__ __align__(128) __half g_h[NE*NT*NI];                       // h hi    [E,4096,512]

__device__ __forceinline__ void split1(float v, __half& h, __half& l) {
    h = __float2half(v);
    l = __float2half(v - __half2float(h));
}

// ---------------- conversion kernels ----------------
__global__ __launch_bounds__(256)
void half_rm(const float4* __restrict__ in, uint2* __restrict__ hi, int n4) {
    int i = blockIdx.x * 256 + threadIdx.x;
    if (i >= n4) return;
    float4 v = in[i];
    __half h[4] = {__float2half(v.x), __float2half(v.y),
                   __float2half(v.z), __float2half(v.w)};
    hi[i] = *(uint2*)h;
}

// in: [E, R, C] fp32 -> out hi: [E, C, R]
__global__ __launch_bounds__(256)
void half_tr(const float* __restrict__ in, __half* __restrict__ hi, int R, int C) {
    __shared__ float t[32][33];
    const int e = blockIdx.z;
    const float* ine = in + (size_t)e * R * C;
    __half* he = hi + (size_t)e * R * C;
    const int r0 = blockIdx.y * 32, c0 = blockIdx.x * 32;
    const int tx = threadIdx.x & 31, ty = threadIdx.x >> 5;
    #pragma unroll
    for (int i = 0; i < 32; i += 8)
        t[ty + i][tx] = ine[(size_t)(r0 + ty + i) * C + c0 + tx];
    __syncthreads();
    #pragma unroll
    for (int i = 0; i < 32; i += 8)
        he[(size_t)(c0 + ty + i) * R + r0 + tx] = __float2half(t[tx][ty + i]);
}

// in: [E, R, C] fp32 -> out hi/lo: [E, C, R]
__global__ __launch_bounds__(256)
void split_tr(const float* __restrict__ in, __half* __restrict__ hi,
              __half* __restrict__ lo, int R, int C) {
    __shared__ float t[32][33];
    const int e = blockIdx.z;
    const float* ine = in + (size_t)e * R * C;
    __half* he = hi + (size_t)e * R * C;
    __half* le = lo + (size_t)e * R * C;
    const int r0 = blockIdx.y * 32, c0 = blockIdx.x * 32;
    const int tx = threadIdx.x & 31, ty = threadIdx.x >> 5;
    #pragma unroll
    for (int i = 0; i < 32; i += 8)
        t[ty + i][tx] = ine[(size_t)(r0 + ty + i) * C + c0 + tx];
    __syncthreads();
    #pragma unroll
    for (int i = 0; i < 32; i += 8) {
        __half h, l;
        split1(t[tx][ty + i], h, l);
        he[(size_t)(c0 + ty + i) * R + r0 + tx] = h;
        le[(size_t)(c0 + ty + i) * R + r0 + tx] = l;
    }
}

// ---------------- common HMMA pieces ----------------
#define BM 128
#define BN 128

__device__ __forceinline__ void cp16(uint32_t s, const void* g) {
    asm volatile("cp.async.cg.shared.global [%0], [%1], 16;" :: "r"(s), "l"(g));
}
__device__ __forceinline__ void ldm4(uint32_t* r, uint32_t addr) {
    asm volatile("ldmatrix.sync.aligned.m8n8.x4.shared.b16 {%0,%1,%2,%3}, [%4];"
                 : "=r"(r[0]), "=r"(r[1]), "=r"(r[2]), "=r"(r[3]) : "r"(addr));
}
__device__ __forceinline__ void mma16816(float* c, const uint32_t* a, uint32_t b0, uint32_t b1) {
    asm volatile("mma.sync.aligned.m16n8k16.row.col.f32.f16.f16.f32 "
                 "{%0,%1,%2,%3}, {%4,%5,%6,%7}, {%8,%9}, {%0,%1,%2,%3};"
                 : "+f"(c[0]), "+f"(c[1]), "+f"(c[2]), "+f"(c[3])
                 : "r"(a[0]), "r"(a[1]), "r"(a[2]), "r"(a[3]), "r"(b0), "r"(b1));
}

// ---------------- 2-term prep GEMM: BKC=32, 3-stage (proven) ----------------
#define BKC 32
#define ROWB 80u
#define TILEB (128u * ROWB)
#define SMEM_2T (3u * 3u * TILEB)   // 92160

template<int OUTMODE>   // 1 = split hi/lo, 2 = hi only
__global__ __launch_bounds__(256, 2)
void gemm_2t(const __half* __restrict__ Ah,
             const __half* __restrict__ Bh, const __half* __restrict__ Bl,
             __half* __restrict__ Ch, __half* __restrict__ Cl,
             int M, int N, int K)
{
    constexpr uint32_t BUFB = 3u * TILEB;
    constexpr int NST = 3;

    extern __shared__ __align__(128) char smem[];
    const uint32_t sb = (uint32_t)__cvta_generic_to_shared(smem);

    const int tid = threadIdx.x;
    const int lane = tid & 31;
    const int wid = tid >> 5;
    const int wm = (wid >> 2) * 64;
    const int wn = (wid & 3) * 32;
    const int g = lane >> 3, r8 = lane & 7;

    const int e = blockIdx.z;
    const size_t MK = (size_t)M * K, NK = (size_t)N * K, MN = (size_t)M * N;
    const __half *Ahe = Ah + e * MK;
    const __half *Bhe = Bh + e * NK, *Ble = Bl + e * NK;
    const int bm = blockIdx.y * BM, bn = blockIdx.x * BN;

    float acc[4][4][4];
    #pragma unroll
    for (int i = 0; i < 4; i++)
        #pragma unroll
        for (int j = 0; j < 4; j++)
            #pragma unroll
            for (int q = 0; q < 4; q++) acc[i][j][q] = 0.0f;

    const int NC = K / BKC;
    const int cr0 = tid >> 2,          cc0 = tid & 3;
    const int cr1 = (tid + 256) >> 2,  cc1 = (tid + 256) & 3;

    auto load_chunk = [&](int c, int buf) {
        const int k0 = c * BKC;
        const uint32_t b = sb + (uint32_t)buf * BUFB;
        cp16(b + cr0 * ROWB + cc0 * 16, Ahe + (size_t)(bm + cr0) * K + k0 + cc0 * 8);
        cp16(b + cr1 * ROWB + cc1 * 16, Ahe + (size_t)(bm + cr1) * K + k0 + cc1 * 8);
        cp16(b + TILEB + cr0 * ROWB + cc0 * 16, Bhe + (size_t)(bn + cr0) * K + k0 + cc0 * 8);
        cp16(b + TILEB + cr1 * ROWB + cc1 * 16, Bhe + (size_t)(bn + cr1) * K + k0 + cc1 * 8);
        cp16(b + 2 * TILEB + cr0 * ROWB + cc0 * 16, Ble + (size_t)(bn + cr0) * K + k0 + cc0 * 8);
        cp16(b + 2 * TILEB + cr1 * ROWB + cc1 * 16, Ble + (size_t)(bn + cr1) * K + k0 + cc1 * 8);
        asm volatile("cp.async.commit_group;" ::: "memory");
    };

    load_chunk(0, 0);
    load_chunk(1, 1);

    for (int c = 0; c < NC; c++) {
        asm volatile("cp.async.wait_group 1;" ::: "memory");
        __syncthreads();
        if (c + 2 < NC) load_chunk(c + 2, (c + 2) % NST);
        else asm volatile("cp.async.commit_group;" ::: "memory");

        const uint32_t As = sb + (uint32_t)(c % NST) * BUFB;
        const uint32_t Bs  = As + TILEB;
        const uint32_t Bls = As + 2 * TILEB;

        #pragma unroll
        for (int ks = 0; ks < 2; ks++) {
            uint32_t ah[4][4], bbh[2][4], bbl[2][4];
            #pragma unroll
            for (int ti = 0; ti < 4; ti++) {
                uint32_t off = (uint32_t)(wm + ti * 16 + (g & 1) * 8 + r8) * ROWB
                             + ks * 32 + (g >> 1) * 16;
                ldm4(ah[ti], As + off);
            }
            #pragma unroll
            for (int p = 0; p < 2; p++) {
                uint32_t off = (uint32_t)(wn + p * 16 + (g >> 1) * 8 + r8) * ROWB
                             + ks * 32 + (g & 1) * 16;
                ldm4(bbh[p], Bs + off);
                ldm4(bbl[p], Bls + off);
            }
            #pragma unroll
            for (int ti = 0; ti < 4; ti++)
                #pragma unroll
                for (int tj = 0; tj < 4; tj++) {
                    mma16816(acc[ti][tj], ah[ti],
                             bbh[tj >> 1][(tj & 1) * 2], bbh[tj >> 1][(tj & 1) * 2 + 1]);
                    mma16816(acc[ti][tj], ah[ti],
                             bbl[tj >> 1][(tj & 1) * 2], bbl[tj >> 1][(tj & 1) * 2 + 1]);
                }
        }
    }

    #pragma unroll
    for (int ti = 0; ti < 4; ti++)
        #pragma unroll
        for (int tj = 0; tj < 4; tj++) {
            const int row = bm + wm + ti * 16 + (lane >> 2);
            const int col = bn + wn + tj * 8 + (lane & 3) * 2;
            if (OUTMODE == 1) {
                __half h0, l0, h1, l1;
                split1(acc[ti][tj][0], h0, l0); split1(acc[ti][tj][1], h1, l1);
                __half hp[2] = {h0, h1}, lp[2] = {l0, l1};
                *(uint32_t*)(Ch + e * MN + (size_t)row * N + col) = *(uint32_t*)hp;
                *(uint32_t*)(Cl + e * MN + (size_t)row * N + col) = *(uint32_t*)lp;
                split1(acc[ti][tj][2], h0, l0); split1(acc[ti][tj][3], h1, l1);
                __half hq[2] = {h0, h1}, lq[2] = {l0, l1};
                *(uint32_t*)(Ch + e * MN + (size_t)(row + 8) * N + col) = *(uint32_t*)hq;
                *(uint32_t*)(Cl + e * MN + (size_t)(row + 8) * N + col) = *(uint32_t*)lq;
            } else {
                __half hp[2] = {__float2half(acc[ti][tj][0]), __float2half(acc[ti][tj][1])};
                __half hq[2] = {__float2half(acc[ti][tj][2]), __float2half(acc[ti][tj][3])};
                *(uint32_t*)(Ch + e * MN + (size_t)row * N + col) = *(uint32_t*)hp;
                *(uint32_t*)(Ch + e * MN + (size_t)(row + 8) * N + col) = *(uint32_t*)hq;
            }
        }
}

// ---------------- 1-term GEMM: BK=64, 3-stage, 144B rows ----------------
#define ROW64 144u
#define TILE64 (128u * ROW64)        // 18432 B per 128x64 tile
#define STAGE64 (2u * TILE64)        // A + B = 36864 B
#define SMEM_1T (3u * STAGE64)       // 110592 B (x2 CTAs = 221KB/SM)

template<int OUTMODE>   // 0 = fp32, 2 = hi only
__global__ __launch_bounds__(256, 2)
void gemm_1t64(const __half* __restrict__ Ah, const __half* __restrict__ Bh,
               float* __restrict__ Cf, __half* __restrict__ Ch,
               int M, int N, int K)
{
    constexpr int NST = 3;

    extern __shared__ __align__(128) char smem[];
    const uint32_t sb = (uint32_t)__cvta_generic_to_shared(smem);

    const int tid = threadIdx.x;
    const int lane = tid & 31;
    const int wid = tid >> 5;
    const int wm = (wid >> 2) * 64;
    const int wn = (wid & 3) * 32;
    const int g = lane >> 3, r8 = lane & 7;

    const int e = blockIdx.z;
    const size_t MK = (size_t)M * K, NK = (size_t)N * K, MN = (size_t)M * N;
    const __half *Ahe = Ah + e * MK;
    const __half *Bhe = Bh + e * NK;
    const int bm = blockIdx.y * BM, bn = blockIdx.x * BN;

    float acc[4][4][4];
    #pragma unroll
    for (int i = 0; i < 4; i++)
        #pragma unroll
        for (int j = 0; j < 4; j++)
            #pragma unroll
            for (int q = 0; q < 4; q++) acc[i][j][q] = 0.0f;

    const int NS = K >> 6;   // stages of 64

    auto load_stage = [&](int s, int buf) {
        const int k0 = s << 6;
        const uint32_t b = sb + (uint32_t)buf * STAGE64;
        #pragma unroll
        for (int u = 0; u < 4; u++) {
            const int unit = tid + u * 256;       // 0..1023
            const int row = unit >> 3, cc = unit & 7;
            cp16(b + row * ROW64 + cc * 16,
                 Ahe + (size_t)(bm + row) * K + k0 + cc * 8);
            cp16(b + TILE64 + row * ROW64 + cc * 16,
                 Bhe + (size_t)(bn + row) * K + k0 + cc * 8);
        }
        asm volatile("cp.async.commit_group;" ::: "memory");
    };

    load_stage(0, 0);
    load_stage(1, 1);

    for (int s = 0; s < NS; s++) {
        asm volatile("cp.async.wait_group 1;" ::: "memory");
        __syncthreads();
        if (s + 2 < NS) load_stage(s + 2, (s + 2) % NST);
        else asm volatile("cp.async.commit_group;" ::: "memory");

        const uint32_t As = sb + (uint32_t)(s % NST) * STAGE64;
        const uint32_t Bs = As + TILE64;

        #pragma unroll
        for (int ks = 0; ks < 4; ks++) {
            uint32_t ah[4][4], bbh[2][4];
            #pragma unroll
            for (int ti = 0; ti < 4; ti++) {
                uint32_t off = (uint32_t)(wm + ti * 16 + (g & 1) * 8 + r8) * ROW64
                             + ks * 32 + (g >> 1) * 16;
                ldm4(ah[ti], As + off);
            }
            #pragma unroll
            for (int p = 0; p < 2; p++) {
                uint32_t off = (uint32_t)(wn + p * 16 + (g >> 1) * 8 + r8) * ROW64
                             + ks * 32 + (g & 1) * 16;
                ldm4(bbh[p], Bs + off);
            }
            #pragma unroll
            for (int ti = 0; ti < 4; ti++)
                #pragma unroll
                for (int tj = 0; tj < 4; tj++)
                    mma16816(acc[ti][tj], ah[ti],
                             bbh[tj >> 1][(tj & 1) * 2], bbh[tj >> 1][(tj & 1) * 2 + 1]);
        }
    }

    #pragma unroll
    for (int ti = 0; ti < 4; ti++)
        #pragma unroll
        for (int tj = 0; tj < 4; tj++) {
            const int row = bm + wm + ti * 16 + (lane >> 2);
            const int col = bn + wn + tj * 8 + (lane & 3) * 2;
            if (OUTMODE == 2) {
                __half hp[2] = {__float2half(acc[ti][tj][0]), __float2half(acc[ti][tj][1])};
                __half hq[2] = {__float2half(acc[ti][tj][2]), __float2half(acc[ti][tj][3])};
                *(uint32_t*)(Ch + e * MN + (size_t)row * N + col) = *(uint32_t*)hp;
                *(uint32_t*)(Ch + e * MN + (size_t)(row + 8) * N + col) = *(uint32_t*)hq;
            } else {
                float* cp0 = Cf + e * MN + (size_t)row * N + col;
                float* cp1 = Cf + e * MN + (size_t)(row + 8) * N + col;
                *(float2*)cp0 = make_float2(acc[ti][tj][0], acc[ti][tj][1]);
                *(float2*)cp1 = make_float2(acc[ti][tj][2], acc[ti][tj][3]);
            }
        }
}

// ---------------- launcher ----------------
extern "C" void kernel_launch(void* const* d_in, const int* in_sizes, int n_in,
                              void* d_out, int out_size)
{
    (void)in_sizes; (void)n_in; (void)out_size;
    const float* x  = (const float*)d_in[0];
    const float* w1 = (const float*)d_in[1];
    const float* w2 = (const float*)d_in[2];
    const float* w3 = (const float*)d_in[3];
    const float* w4 = (const float*)d_in[4];
    float* out = (float*)d_out;

    __half *xh,*w1th,*w2h,*w3th,*w3tl,*w4th,*Ph,*Pl,*Vth,*hbuf;
    cudaGetSymbolAddress((void**)&xh,   g_xh);
    cudaGetSymbolAddress((void**)&w1th, g_w1th);
    cudaGetSymbolAddress((void**)&w2h,  g_w2h);
    cudaGetSymbolAddress((void**)&w3th, g_w3th); cudaGetSymbolAddress((void**)&w3tl, g_w3tl);
    cudaGetSymbolAddress((void**)&w4th, g_w4th);
    cudaGetSymbolAddress((void**)&Ph,   g_Ph);   cudaGetSymbolAddress((void**)&Pl,   g_Pl);
    cudaGetSymbolAddress((void**)&Vth,  g_Vth);
    cudaGetSymbolAddress((void**)&hbuf, g_h);

    cudaFuncSetAttribute(gemm_2t<1>, cudaFuncAttributeMaxDynamicSharedMemorySize, SMEM_2T);
    cudaFuncSetAttribute(gemm_2t<2>, cudaFuncAttributeMaxDynamicSharedMemorySize, SMEM_2T);
    cudaFuncSetAttribute(gemm_1t64<0>, cudaFuncAttributeMaxDynamicSharedMemorySize, SMEM_1T);
    cudaFuncSetAttribute(gemm_1t64<2>, cudaFuncAttributeMaxDynamicSharedMemorySize, SMEM_1T);

    // idx 0: w1 -> w1^T hi
    half_tr<<<dim3(NI / 32, NH / 32, NE), 256>>>(w1, w1th, NH, NI);
    // idx 1: x hi
    {
        int n4 = NE * NT * NH / 4;
        half_rm<<<n4 / 256, 256>>>((const float4*)x, (uint2*)xh, n4);
    }
    // idx 2: w3 -> w3^T hi/lo
    split_tr<<<dim3(NI / 32, NH / 32, NE), 256>>>(w3, w3th, w3tl, NH, NI);
    // idx 3 (ncu capture): h = x @ w1 (1-term, BK=64)  M=4096, N=512, K=1024
    gemm_1t64<2><<<dim3(NI / BN, NT / BM, NE), 256, SMEM_1T>>>(
        xh, w1th, nullptr, hbuf, NT, NI, NH);
    // idx 4: w2 hi
    {
        int n4 = NE * NI * NH / 4;
        half_rm<<<n4 / 256, 256>>>((const float4*)w2, (uint2*)w2h, n4);
    }
    // idx 5: P = w2 @ w3 (2-term, split out)  M=N=512, K=1024
    gemm_2t<1><<<dim3(NI / BN, NI / BM, NE), 256, SMEM_2T>>>(
        w2h, w3th, w3tl, Ph, Pl, NI, NI, NH);
    // idx 6: w4 -> w4^T hi
    half_tr<<<dim3(NH / 32, NI / 32, NE), 256>>>(w4, w4th, NI, NH);
    // idx 7: V^T = w4^T @ P^T (2-term, hi out)  M=1024, N=512, K=512
    gemm_2t<2><<<dim3(NI / BN, NH / BM, NE), 256, SMEM_2T>>>(
        w4th, Ph, Pl, Vth, nullptr, NH, NI, NI);
    // idx 8: out = h @ V (1-term, BK=64, fp32 out)  M=4096, N=1024, K=512
    gemm_1t64<0><<<dim3(NH / BN, NT / BM, NE), 256, SMEM_1T>>>(
        hbuf, Vth, out, nullptr, NT, NH, NI);
}